// round 6
// baseline (speedup 1.0000x reference)
#include <cuda_runtime.h>
#include <cuda_fp16.h>
#include <cstdint>
#include <math.h>

#define B_ 4
#define T_ 4096
#define C_ 1024
#define H_ 128

// fp16 staging (static: allocation-free per harness rules)
__device__ __half g_X [B_ * T_ * C_];     // x as fp16            [bt][k]
__device__ __half g_WT[3 * H_ * C_];      // W^T fp16             [which][n][k]
__device__ __half g_Q [B_ * T_ * H_];
__device__ __half g_K [B_ * T_ * H_];
__device__ __half g_V [B_ * T_ * H_];

__device__ __forceinline__ uint32_t h2u(__half2 h) { return *reinterpret_cast<uint32_t*>(&h); }

__device__ __forceinline__ void mma_f16(float c[4], const uint32_t a[4],
                                        uint32_t b0, uint32_t b1) {
    asm volatile(
        "mma.sync.aligned.m16n8k16.row.col.f32.f16.f16.f32 "
        "{%0,%1,%2,%3}, {%4,%5,%6,%7}, {%8,%9}, {%0,%1,%2,%3};"
        : "+f"(c[0]), "+f"(c[1]), "+f"(c[2]), "+f"(c[3])
        : "r"(a[0]), "r"(a[1]), "r"(a[2]), "r"(a[3]), "r"(b0), "r"(b1));
}
__device__ __forceinline__ void ldsm4(uint32_t& r0, uint32_t& r1, uint32_t& r2,
                                      uint32_t& r3, uint32_t addr) {
    asm volatile("ldmatrix.sync.aligned.m8n8.x4.shared.b16 {%0,%1,%2,%3}, [%4];"
                 : "=r"(r0), "=r"(r1), "=r"(r2), "=r"(r3) : "r"(addr));
}
__device__ __forceinline__ void ldsm4t(uint32_t& r0, uint32_t& r1, uint32_t& r2,
                                       uint32_t& r3, uint32_t addr) {
    asm volatile("ldmatrix.sync.aligned.m8n8.x4.trans.shared.b16 {%0,%1,%2,%3}, [%4];"
                 : "=r"(r0), "=r"(r1), "=r"(r2), "=r"(r3) : "r"(addr));
}
__device__ __forceinline__ void cp16(uint32_t dst, const void* src) {
    asm volatile("cp.async.cg.shared.global [%0], [%1], 16;" :: "r"(dst), "l"(src));
}
__device__ __forceinline__ uint32_t ex2_f16x2(uint32_t x) {
    uint32_t r;
    asm("ex2.approx.f16x2 %0, %1;" : "=r"(r) : "r"(x));
    return r;
}

// ---------------------------------------------------------------------------
// Conversion kernels (HBM bound, one-shot)
// ---------------------------------------------------------------------------
__global__ __launch_bounds__(256)
void cvt_x_kernel(const float* __restrict__ x)
{
    int i = (blockIdx.x * 256 + threadIdx.x) * 8;
    float4 a = *reinterpret_cast<const float4*>(x + i);
    float4 b = *reinterpret_cast<const float4*>(x + i + 4);
    uint4 o;
    o.x = h2u(__floats2half2_rn(a.x, a.y));
    o.y = h2u(__floats2half2_rn(a.z, a.w));
    o.z = h2u(__floats2half2_rn(b.x, b.y));
    o.w = h2u(__floats2half2_rn(b.z, b.w));
    *reinterpret_cast<uint4*>(&g_X[i]) = o;
}

__global__ __launch_bounds__(256)
void cvt_w_kernel(const float* __restrict__ Wq,
                  const float* __restrict__ Wk,
                  const float* __restrict__ Wv)
{
    int idx = blockIdx.x * 256 + threadIdx.x;       // 3*128*1024
    int which = idx >> 17;
    int r = idx & 131071;
    int n = r >> 10, k = r & 1023;
    const float* W = (which == 0) ? Wq : (which == 1) ? Wk : Wv;
    g_WT[idx] = __float2half(W[k * H_ + n]);
}

// ---------------------------------------------------------------------------
// Projection GEMM: out[16384,128](fp16) = X @ W (B as W^T [n][k]).
// CTA = 128m x 128n; k-chunks of 64, double-buffered; 2 CTAs/SM.
// ---------------------------------------------------------------------------
#define PJ 72                           // halves per tile row (k-chunk 64)
#define PJ_TILE (128 * PJ)
#define PA0 0
#define PA1 PJ_TILE
#define PB0 (2 * PJ_TILE)
#define PB1 (3 * PJ_TILE)
#define PROJ_SMEM (4 * PJ_TILE * 2)     // 73728 B

__global__ __launch_bounds__(256, 2)
void proj_kernel()
{
    extern __shared__ __half psm[];
    const uint32_t sm_b = (uint32_t)__cvta_generic_to_shared(psm);

    const int tid  = threadIdx.x;
    const int warp = tid >> 5;
    const int lane = tid & 31;
    const int g    = lane >> 2;
    const int t4   = lane & 3;
    const int m0   = blockIdx.x * 128;
    const int which = blockIdx.y;
    __half* __restrict__ outp = (which == 0) ? g_Q : (which == 1) ? g_K : g_V;
    const __half* __restrict__ Asrc = g_X + (size_t)m0 * C_;
    const __half* __restrict__ Bsrc = g_WT + (size_t)which * H_ * C_;

    const int aoff = ((lane & 8) + (lane & 7)) * PJ + ((lane & 16) >> 1);
    const int koff = (((lane & 16) >> 1) + (lane & 7)) * PJ + ((lane & 8) ? 8 : 0);

    float acc[16][4];
#pragma unroll
    for (int i = 0; i < 16; i++)
#pragma unroll
        for (int j = 0; j < 4; j++) acc[i][j] = 0.f;

    auto fill = [&](int kb, int stg) {
        uint32_t ab = sm_b + (stg ? PA1 : PA0) * 2;
        uint32_t bb = sm_b + (stg ? PB1 : PB0) * 2;
#pragma unroll
        for (int it = 0; it < 4; it++) {
            int u = tid + it * 256;
            int row = u >> 3, q = u & 7;
            cp16(ab + (row * PJ + q * 8) * 2, Asrc + (size_t)row * C_ + kb + q * 8);
            cp16(bb + (row * PJ + q * 8) * 2, Bsrc + (size_t)row * C_ + kb + q * 8);
        }
        asm volatile("cp.async.commit_group;");
    };

    fill(0, 0);
    for (int c = 0; c < 16; c++) {
        if (c + 1 < 16) {
            fill((c + 1) * 64, (c + 1) & 1);
            asm volatile("cp.async.wait_group 1;");
        } else {
            asm volatile("cp.async.wait_group 0;");
        }
        __syncthreads();

        const uint32_t ab = sm_b + ((c & 1) ? PA1 : PA0) * 2;
        const uint32_t bb = sm_b + ((c & 1) ? PB1 : PB0) * 2;
#pragma unroll
        for (int kk = 0; kk < 4; kk++) {
            uint32_t a[4];
            ldsm4(a[0], a[1], a[2], a[3],
                  ab + (warp * 16 * PJ + kk * 16 + aoff) * 2);
#pragma unroll
            for (int nbp = 0; nbp < 8; nbp++) {
                uint32_t b0, b1, b2, b3;
                ldsm4(b0, b1, b2, b3,
                      bb + (nbp * 16 * PJ + kk * 16 + koff) * 2);
                mma_f16(acc[2 * nbp],     a, b0, b1);
                mma_f16(acc[2 * nbp + 1], a, b2, b3);
            }
        }
        __syncthreads();
    }

    const int r0 = m0 + warp * 16 + g;
#pragma unroll
    for (int nb = 0; nb < 16; nb++) {
        int cc = nb * 8 + 2 * t4;
        *reinterpret_cast<uint32_t*>(&outp[(size_t)r0 * H_ + cc]) =
            h2u(__floats2half2_rn(acc[nb][0], acc[nb][1]));
        *reinterpret_cast<uint32_t*>(&outp[(size_t)(r0 + 8) * H_ + cc]) =
            h2u(__floats2half2_rn(acc[nb][2], acc[nb][3]));
    }
}

// ---------------------------------------------------------------------------
// Flash attention: CTA = (batch, 64 q-rows), 384 threads = 3 kv-groups x 4 warps.
// Group gid sweeps tiles {3r+gid}; independent online softmax per group;
// split-KV merge in smem at the end. 6 cp.async stages.
// ---------------------------------------------------------------------------
#define KT 136
#define VOFF_H (64 * KT)                // 8704 halves
#define ST_H (2 * 64 * KT)              // 17408 halves per stage (K+V)
#define NSTG 6
#define ATTN_SMEM (NSTG * ST_H * 2)     // 208896 B
#define RNDS 22                          // ceil(64 tiles / 3 groups)

__global__ __launch_bounds__(384, 1)
void attn_kernel(float* __restrict__ out)
{
    extern __shared__ __half sm[];
    const uint32_t sm_b = (uint32_t)__cvta_generic_to_shared(sm);

    const int tid  = threadIdx.x;
    const int wid  = tid >> 5;
    const int lane = tid & 31;
    const int g    = lane >> 2;
    const int t4   = lane & 3;
    const int gid  = wid >> 2;        // kv-group 0..2
    const int mw   = wid & 3;         // m-warp within group 0..3
    const int b    = blockIdx.y;
    const int q0   = blockIdx.x * 64;

    const __half* __restrict__ Q = g_Q + (size_t)b * T_ * H_;
    const __half* __restrict__ K = g_K + (size_t)b * T_ * H_;
    const __half* __restrict__ V = g_V + (size_t)b * T_ * H_;

    const int koff = (((lane & 16) >> 1) + (lane & 7)) * KT + ((lane & 8) ? 8 : 0);
    const int voff = ((lane & 8) + (lane & 7)) * KT + ((lane & 16) >> 1);

    // Q fragments (fp16 bits), rows q0 + mw*16 + g (+8)
    uint32_t qa[8][4];
    const int rg  = q0 + mw * 16 + g;
    const int rg8 = rg + 8;
#pragma unroll
    for (int kk = 0; kk < 8; kk++) {
        qa[kk][0] = *reinterpret_cast<const uint32_t*>(&Q[(size_t)rg  * H_ + kk * 16 + 2 * t4]);
        qa[kk][1] = *reinterpret_cast<const uint32_t*>(&Q[(size_t)rg8 * H_ + kk * 16 + 2 * t4]);
        qa[kk][2] = *reinterpret_cast<const uint32_t*>(&Q[(size_t)rg  * H_ + kk * 16 + 2 * t4 + 8]);
        qa[kk][3] = *reinterpret_cast<const uint32_t*>(&Q[(size_t)rg8 * H_ + kk * 16 + 2 * t4 + 8]);
    }

    float o[16][4];
#pragma unroll
    for (int i = 0; i < 16; i++)
#pragma unroll
        for (int j = 0; j < 4; j++) o[i][j] = 0.f;

    float mrun[2] = {-INFINITY, -INFINITY};
    float lsum[2] = {0.f, 0.f};
    const float SC = 0.04508422f;     // 1024^-0.5 * log2(e)

    // Fill all (valid) tiles of round rr into stages (j*2 + rr&1).
    auto fill_round = [&](int rr) {
        int p = rr & 1;
#pragma unroll
        for (int it = 0; it < 16; it++) {
            int u = tid + it * 384;
            int j = u >> 11;                  // which group's tile (2048 cp16 each)
            int w = u & 2047;
            int t = 3 * rr + j;
            if (t < 64) {
                int isv = (w >> 10) & 1;
                int row = (w & 1023) >> 4;
                int q   = w & 15;
                const __half* src = (isv ? V : K) + (size_t)(t * 64 + row) * H_ + q * 8;
                uint32_t dst = sm_b + ((uint32_t)((j * 2 + p) * ST_H + isv * VOFF_H
                                                  + row * KT + q * 8)) * 2;
                cp16(dst, src);
            }
        }
        asm volatile("cp.async.commit_group;");
    };

    fill_round(0);
    fill_round(1);

    for (int r = 0; r < RNDS; r++) {
        if (r + 1 < RNDS) {
            asm volatile("cp.async.wait_group 1;");
        } else {
            asm volatile("cp.async.wait_group 0;");
        }
        __syncthreads();

        const int t = 3 * r + gid;
        if (t < 64) {
            const uint32_t kbh = (uint32_t)((gid * 2 + (r & 1)) * ST_H);
            const uint32_t vbh = kbh + VOFF_H;

            // S = Q K^T : 16x64 per warp
            float s[8][4];
#pragma unroll
            for (int n = 0; n < 8; n++)
#pragma unroll
                for (int j = 0; j < 4; j++) s[n][j] = 0.f;
#pragma unroll
            for (int kk = 0; kk < 8; kk++) {
#pragma unroll
                for (int nbp = 0; nbp < 4; nbp++) {
                    uint32_t b0, b1, b2, b3;
                    ldsm4(b0, b1, b2, b3,
                          sm_b + (kbh + nbp * 16 * KT + kk * 16 + koff) * 2);
                    mma_f16(s[2 * nbp],     qa[kk], b0, b1);
                    mma_f16(s[2 * nbp + 1], qa[kk], b2, b3);
                }
            }

            // Online softmax; exp via ex2.f16x2 -> P in fragment form
#pragma unroll
            for (int n = 0; n < 8; n++)
#pragma unroll
                for (int j = 0; j < 4; j++) s[n][j] *= SC;

            float alpha[2];
            uint32_t ph2[8][2];
#pragma unroll
            for (int hr = 0; hr < 2; hr++) {
                float mx = -INFINITY;
#pragma unroll
                for (int n = 0; n < 8; n++)
                    mx = fmaxf(mx, fmaxf(s[n][2 * hr], s[n][2 * hr + 1]));
                mx = fmaxf(mx, __shfl_xor_sync(0xffffffffu, mx, 1));
                mx = fmaxf(mx, __shfl_xor_sync(0xffffffffu, mx, 2));
                float mn = fmaxf(mrun[hr], mx);
                alpha[hr] = exp2f(mrun[hr] - mn);
                float sum = 0.f;
#pragma unroll
                for (int n = 0; n < 8; n++) {
                    __half2 hh = __floats2half2_rn(s[n][2 * hr] - mn, s[n][2 * hr + 1] - mn);
                    uint32_t e = ex2_f16x2(h2u(hh));
                    ph2[n][hr] = e;
                    float2 f = __half22float2(*reinterpret_cast<__half2*>(&e));
                    sum += f.x + f.y;
                }
                sum += __shfl_xor_sync(0xffffffffu, sum, 1);
                sum += __shfl_xor_sync(0xffffffffu, sum, 2);
                lsum[hr] = lsum[hr] * alpha[hr] + sum;
                mrun[hr] = mn;
            }
#pragma unroll
            for (int n = 0; n < 16; n++) {
                o[n][0] *= alpha[0]; o[n][1] *= alpha[0];
                o[n][2] *= alpha[1]; o[n][3] *= alpha[1];
            }

            // O += P V : P register-resident as A-fragments
#pragma unroll
            for (int kk = 0; kk < 4; kk++) {
                uint32_t a[4] = {ph2[2 * kk][0], ph2[2 * kk][1],
                                 ph2[2 * kk + 1][0], ph2[2 * kk + 1][1]};
#pragma unroll
                for (int nbp = 0; nbp < 8; nbp++) {
                    uint32_t b0, b1, b2, b3;
                    ldsm4t(b0, b1, b2, b3,
                           sm_b + (vbh + kk * 16 * KT + nbp * 16 + voff) * 2);
                    mma_f16(o[2 * nbp],     a, b0, b1);
                    mma_f16(o[2 * nbp + 1], a, b2, b3);
                }
            }
        }
        __syncthreads();                 // stage consumed before refill
        if (r + 2 < RNDS) fill_round(r + 2);
    }

    // ---- Split-KV merge across the 3 groups (smem) --------------------------
    __syncthreads();
    float* fsm  = reinterpret_cast<float*>(sm);
    float* Mg   = fsm;            // [3][64]
    float* Lg   = fsm + 192;      // [3][64]
    float* InvL = fsm + 384;      // [64]
    float* Oacc = fsm + 448;      // [64][132]

    const int r0l = mw * 16 + g;         // local row in 0..63
    if (t4 == 0) {
        Mg[gid * 64 + r0l]     = mrun[0];  Lg[gid * 64 + r0l]     = lsum[0];
        Mg[gid * 64 + r0l + 8] = mrun[1];  Lg[gid * 64 + r0l + 8] = lsum[1];
    }
    __syncthreads();

    float scl[2];
#pragma unroll
    for (int hr = 0; hr < 2; hr++) {
        int rr = r0l + hr * 8;
        float m0v = Mg[rr], m1v = Mg[64 + rr], m2v = Mg[128 + rr];
        float ms = fmaxf(m0v, fmaxf(m1v, m2v));
        float e0 = exp2f(m0v - ms), e1 = exp2f(m1v - ms), e2 = exp2f(m2v - ms);
        float lt = Lg[rr] * e0 + Lg[64 + rr] * e1 + Lg[128 + rr] * e2;
        scl[hr] = (gid == 0) ? e0 : (gid == 1) ? e1 : e2;
        if (t4 == 0 && gid == 0) InvL[rr] = 1.f / lt;
    }

#pragma unroll
    for (int ph = 0; ph < 3; ph++) {
        if (gid == ph) {
#pragma unroll
            for (int n = 0; n < 16; n++) {
                int cc = n * 8 + 2 * t4;
                float* p0 = &Oacc[r0l * 132 + cc];
                float* p1 = &Oacc[(r0l + 8) * 132 + cc];
                if (ph == 0) {
                    p0[0] = o[n][0] * scl[0]; p0[1] = o[n][1] * scl[0];
                    p1[0] = o[n][2] * scl[1]; p1[1] = o[n][3] * scl[1];
                } else {
                    p0[0] += o[n][0] * scl[0]; p0[1] += o[n][1] * scl[0];
                    p1[0] += o[n][2] * scl[1]; p1[1] += o[n][3] * scl[1];
                }
            }
        }
        __syncthreads();
    }

    // Final write: out[b][q0+row][c] = Oacc / l*
    const size_t obase = (size_t)b * T_ * H_ + (size_t)q0 * H_;
    for (int u = tid; u < 64 * 128; u += 384) {
        int row = u >> 7, cc = u & 127;
        out[obase + (size_t)row * H_ + cc] = Oacc[row * 132 + cc] * InvL[row];
    }
}

extern "C" void kernel_launch(void* const* d_in, const int* in_sizes, int n_in,
                              void* d_out, int out_size)
{
    (void)in_sizes; (void)n_in; (void)out_size;
    const float* x  = (const float*)d_in[0];
    const float* Wk = (const float*)d_in[1];
    const float* Wq = (const float*)d_in[2];
    const float* Wv = (const float*)d_in[3];
    float* out = (float*)d_out;

    cudaFuncSetAttribute(proj_kernel,
                         cudaFuncAttributeMaxDynamicSharedMemorySize, PROJ_SMEM);
    cudaFuncSetAttribute(attn_kernel,
                         cudaFuncAttributeMaxDynamicSharedMemorySize, ATTN_SMEM);

    cvt_x_kernel<<<B_ * T_ * C_ / (256 * 8), 256>>>(x);
    cvt_w_kernel<<<3 * H_ * C_ / 256, 256>>>(Wq, Wk, Wv);

    dim3 pgrid(16384 / 128, 3);
    proj_kernel<<<pgrid, 256, PROJ_SMEM>>>();

    dim3 agrid(T_ / 64, B_);
    attn_kernel<<<agrid, 384, ATTN_SMEM>>>(out);
}

// round 7
// speedup vs baseline: 1.1392x; 1.1392x over previous
#include <cuda_runtime.h>
#include <cuda_fp16.h>
#include <cstdint>
#include <math.h>

#define B_ 4
#define T_ 4096
#define C_ 1024
#define H_ 128

// fp16 staging (static: allocation-free per harness rules)
__device__ __half g_X [B_ * T_ * C_];     // x as fp16            [bt][k]
__device__ __half g_WT[3 * H_ * C_];      // W^T fp16             [which][n][k]
__device__ __half g_Q [B_ * T_ * H_];
__device__ __half g_K [B_ * T_ * H_];
__device__ __half g_V [B_ * T_ * H_];

__device__ __forceinline__ uint32_t h2u(__half2 h) { return *reinterpret_cast<uint32_t*>(&h); }

__device__ __forceinline__ void mma_f16(float c[4], const uint32_t a[4],
                                        uint32_t b0, uint32_t b1) {
    asm volatile(
        "mma.sync.aligned.m16n8k16.row.col.f32.f16.f16.f32 "
        "{%0,%1,%2,%3}, {%4,%5,%6,%7}, {%8,%9}, {%0,%1,%2,%3};"
        : "+f"(c[0]), "+f"(c[1]), "+f"(c[2]), "+f"(c[3])
        : "r"(a[0]), "r"(a[1]), "r"(a[2]), "r"(a[3]), "r"(b0), "r"(b1));
}
__device__ __forceinline__ void ldsm4(uint32_t& r0, uint32_t& r1, uint32_t& r2,
                                      uint32_t& r3, uint32_t addr) {
    asm volatile("ldmatrix.sync.aligned.m8n8.x4.shared.b16 {%0,%1,%2,%3}, [%4];"
                 : "=r"(r0), "=r"(r1), "=r"(r2), "=r"(r3) : "r"(addr));
}
__device__ __forceinline__ void ldsm4t(uint32_t& r0, uint32_t& r1, uint32_t& r2,
                                       uint32_t& r3, uint32_t addr) {
    asm volatile("ldmatrix.sync.aligned.m8n8.x4.trans.shared.b16 {%0,%1,%2,%3}, [%4];"
                 : "=r"(r0), "=r"(r1), "=r"(r2), "=r"(r3) : "r"(addr));
}
__device__ __forceinline__ void cp16(uint32_t dst, const void* src) {
    asm volatile("cp.async.cg.shared.global [%0], [%1], 16;" :: "r"(dst), "l"(src));
}
__device__ __forceinline__ uint32_t ex2_f16x2(uint32_t x) {
    uint32_t r;
    asm("ex2.approx.f16x2 %0, %1;" : "=r"(r) : "r"(x));
    return r;
}

// ---------------------------------------------------------------------------
// Conversion kernels (HBM bound, one-shot)
// ---------------------------------------------------------------------------
__global__ __launch_bounds__(256)
void cvt_x_kernel(const float* __restrict__ x)
{
    int i = (blockIdx.x * 256 + threadIdx.x) * 8;
    float4 a = *reinterpret_cast<const float4*>(x + i);
    float4 b = *reinterpret_cast<const float4*>(x + i + 4);
    uint4 o;
    o.x = h2u(__floats2half2_rn(a.x, a.y));
    o.y = h2u(__floats2half2_rn(a.z, a.w));
    o.z = h2u(__floats2half2_rn(b.x, b.y));
    o.w = h2u(__floats2half2_rn(b.z, b.w));
    *reinterpret_cast<uint4*>(&g_X[i]) = o;
}

__global__ __launch_bounds__(256)
void cvt_w_kernel(const float* __restrict__ Wq,
                  const float* __restrict__ Wk,
                  const float* __restrict__ Wv)
{
    int idx = blockIdx.x * 256 + threadIdx.x;       // 3*128*1024
    int which = idx >> 17;
    int r = idx & 131071;
    int n = r >> 10, k = r & 1023;
    const float* W = (which == 0) ? Wq : (which == 1) ? Wk : Wv;
    g_WT[idx] = __float2half(W[k * H_ + n]);
}

// ---------------------------------------------------------------------------
// Fused projection: Q,K,V[16384,128](fp16) = X @ {Wq,Wk,Wv} in ONE kernel.
// CTA = 128 m-rows; X tile shared across the 3 output matrices.
// k-chunks of 64, double-buffered cp.async. Grid 128 = one wave.
// ---------------------------------------------------------------------------
#define PJ 72                           // halves per tile row (64 + 8 pad)
#define PJT (128 * PJ)                  // halves per [128 x 64] tile
#define PROJ_SMEM (8 * PJT * 2)         // 2 stages x (A + 3 B) = 147456 B

__global__ __launch_bounds__(256)
void proj_kernel()
{
    extern __shared__ __half psm[];
    const uint32_t sm_b = (uint32_t)__cvta_generic_to_shared(psm);

    const int tid  = threadIdx.x;
    const int warp = tid >> 5;
    const int lane = tid & 31;
    const int g    = lane >> 2;
    const int t4   = lane & 3;
    const int m0   = blockIdx.x * 128;
    const __half* __restrict__ Asrc = g_X + (size_t)m0 * C_;

    const int aoff = ((lane & 8) + (lane & 7)) * PJ + ((lane & 16) >> 1);
    const int koff = (((lane & 16) >> 1) + (lane & 7)) * PJ + ((lane & 8) ? 8 : 0);

    float acc[3][16][4];
#pragma unroll
    for (int w = 0; w < 3; w++)
#pragma unroll
        for (int i = 0; i < 16; i++)
#pragma unroll
            for (int j = 0; j < 4; j++) acc[w][i][j] = 0.f;

    auto fill = [&](int kb, int stg) {
        uint32_t base = sm_b + (stg ? 4 * PJT : 0) * 2;
#pragma unroll
        for (int it = 0; it < 4; it++) {
            int u = tid + it * 256;
            int row = u >> 3, q = u & 7;
            cp16(base + (row * PJ + q * 8) * 2, Asrc + (size_t)row * C_ + kb + q * 8);
        }
#pragma unroll
        for (int w = 0; w < 3; w++) {
#pragma unroll
            for (int it = 0; it < 4; it++) {
                int u = tid + it * 256;
                int row = u >> 3, q = u & 7;
                cp16(base + ((1 + w) * PJT + row * PJ + q * 8) * 2,
                     g_WT + (size_t)w * H_ * C_ + (size_t)row * C_ + kb + q * 8);
            }
        }
        asm volatile("cp.async.commit_group;");
    };

    fill(0, 0);
    for (int c = 0; c < 16; c++) {
        if (c + 1 < 16) {
            fill((c + 1) * 64, (c + 1) & 1);
            asm volatile("cp.async.wait_group 1;");
        } else {
            asm volatile("cp.async.wait_group 0;");
        }
        __syncthreads();

        const uint32_t base = sm_b + ((c & 1) ? 4 * PJT : 0) * 2;
#pragma unroll
        for (int kk = 0; kk < 4; kk++) {
            uint32_t a[4];
            ldsm4(a[0], a[1], a[2], a[3],
                  base + (warp * 16 * PJ + kk * 16 + aoff) * 2);
#pragma unroll
            for (int w = 0; w < 3; w++) {
#pragma unroll
                for (int nbp = 0; nbp < 8; nbp++) {
                    uint32_t b0, b1, b2, b3;
                    ldsm4(b0, b1, b2, b3,
                          base + ((1 + w) * PJT + nbp * 16 * PJ + kk * 16 + koff) * 2);
                    mma_f16(acc[w][2 * nbp],     a, b0, b1);
                    mma_f16(acc[w][2 * nbp + 1], a, b2, b3);
                }
            }
        }
        __syncthreads();
    }

    const int r0 = m0 + warp * 16 + g;
#pragma unroll
    for (int w = 0; w < 3; w++) {
        __half* outp = (w == 0) ? g_Q : (w == 1) ? g_K : g_V;
#pragma unroll
        for (int nb = 0; nb < 16; nb++) {
            int cc = nb * 8 + 2 * t4;
            *reinterpret_cast<uint32_t*>(&outp[(size_t)r0 * H_ + cc]) =
                h2u(__floats2half2_rn(acc[w][nb][0], acc[w][nb][1]));
            *reinterpret_cast<uint32_t*>(&outp[(size_t)(r0 + 8) * H_ + cc]) =
                h2u(__floats2half2_rn(acc[w][nb][2], acc[w][nb][3]));
        }
    }
}

// ---------------------------------------------------------------------------
// Flash attention: CTA = (batch, 128 q-rows), 8 warps, KV tile 64,
// double-buffered cp.async. P in registers. Explicit B-fragment double
// buffering in QK and PV loops; V fragments prefetched under softmax.
// ---------------------------------------------------------------------------
#define KT 136
#define K0H 0
#define K1H (64 * KT)
#define V0H (2 * 64 * KT)
#define V1H (3 * 64 * KT)
#define ATTN_SMEM (4 * 64 * KT * 2)    // 69632 B

__global__ __launch_bounds__(256)
void attn_kernel(float* __restrict__ out)
{
    extern __shared__ __half sm[];
    const uint32_t sm_b = (uint32_t)__cvta_generic_to_shared(sm);

    const int tid  = threadIdx.x;
    const int warp = tid >> 5;
    const int lane = tid & 31;
    const int g    = lane >> 2;
    const int t4   = lane & 3;
    const int b    = blockIdx.y;
    const int q0   = blockIdx.x * 128;

    const __half* __restrict__ Q = g_Q + (size_t)b * T_ * H_;
    const __half* __restrict__ K = g_K + (size_t)b * T_ * H_;
    const __half* __restrict__ V = g_V + (size_t)b * T_ * H_;

    const int koff = (((lane & 16) >> 1) + (lane & 7)) * KT + ((lane & 8) ? 8 : 0);
    const int voff = ((lane & 8) + (lane & 7)) * KT + ((lane & 16) >> 1);

    // Q fragments, direct global loads (fp16 bits)
    uint32_t qa[8][4];
    const int rg  = q0 + warp * 16 + g;
    const int rg8 = rg + 8;
#pragma unroll
    for (int kk = 0; kk < 8; kk++) {
        qa[kk][0] = *reinterpret_cast<const uint32_t*>(&Q[(size_t)rg  * H_ + kk * 16 + 2 * t4]);
        qa[kk][1] = *reinterpret_cast<const uint32_t*>(&Q[(size_t)rg8 * H_ + kk * 16 + 2 * t4]);
        qa[kk][2] = *reinterpret_cast<const uint32_t*>(&Q[(size_t)rg  * H_ + kk * 16 + 2 * t4 + 8]);
        qa[kk][3] = *reinterpret_cast<const uint32_t*>(&Q[(size_t)rg8 * H_ + kk * 16 + 2 * t4 + 8]);
    }

    float o[16][4];
#pragma unroll
    for (int i = 0; i < 16; i++)
#pragma unroll
        for (int j = 0; j < 4; j++) o[i][j] = 0.f;

    float mrun[2] = {-INFINITY, -INFINITY};
    float lsum[2] = {0.f, 0.f};
    const float SC = 0.04508422f;     // 1024^-0.5 * log2(e)

    auto issue_tile = [&](int kv, int stg) {
        const __half* Ksrc = K + (size_t)kv * H_;
        const __half* Vsrc = V + (size_t)kv * H_;
        uint32_t kb_ = sm_b + (stg ? K1H : K0H) * 2;
        uint32_t vb_ = sm_b + (stg ? V1H : V0H) * 2;
#pragma unroll
        for (int it = 0; it < 4; it++) {
            int u = tid + it * 256;
            int row = u >> 4, q = u & 15;
            cp16(kb_ + (row * KT + q * 8) * 2, Ksrc + (size_t)row * H_ + q * 8);
            cp16(vb_ + (row * KT + q * 8) * 2, Vsrc + (size_t)row * H_ + q * 8);
        }
        asm volatile("cp.async.commit_group;");
    };

    const int NT = T_ / 64;
    issue_tile(0, 0);

    for (int i = 0; i < NT; i++) {
        if (i + 1 < NT) {
            issue_tile((i + 1) * 64, (i + 1) & 1);
            asm volatile("cp.async.wait_group 1;");
        } else {
            asm volatile("cp.async.wait_group 0;");
        }
        __syncthreads();

        const uint32_t kbh = (i & 1) ? K1H : K0H;
        const uint32_t vbh = (i & 1) ? V1H : V0H;

        // ---- S = Q K^T, K-fragments double-buffered across k-steps ----------
        float s[8][4];
#pragma unroll
        for (int n = 0; n < 8; n++)
#pragma unroll
            for (int j = 0; j < 4; j++) s[n][j] = 0.f;

        uint32_t kf[2][16];
#pragma unroll
        for (int nbp = 0; nbp < 4; nbp++)
            ldsm4(kf[0][4 * nbp], kf[0][4 * nbp + 1], kf[0][4 * nbp + 2], kf[0][4 * nbp + 3],
                  sm_b + (kbh + nbp * 16 * KT + koff) * 2);
#pragma unroll
        for (int kk = 0; kk < 8; kk++) {
            const int cur = kk & 1;
            if (kk < 7) {
#pragma unroll
                for (int nbp = 0; nbp < 4; nbp++)
                    ldsm4(kf[cur ^ 1][4 * nbp], kf[cur ^ 1][4 * nbp + 1],
                          kf[cur ^ 1][4 * nbp + 2], kf[cur ^ 1][4 * nbp + 3],
                          sm_b + (kbh + nbp * 16 * KT + (kk + 1) * 16 + koff) * 2);
            }
#pragma unroll
            for (int nbp = 0; nbp < 4; nbp++) {
                mma_f16(s[2 * nbp],     qa[kk], kf[cur][4 * nbp],     kf[cur][4 * nbp + 1]);
                mma_f16(s[2 * nbp + 1], qa[kk], kf[cur][4 * nbp + 2], kf[cur][4 * nbp + 3]);
            }
        }

        // ---- Prefetch first PV V-fragment batch (independent of softmax) ----
        uint32_t vf[2][32];
#pragma unroll
        for (int nbp = 0; nbp < 8; nbp++)
            ldsm4t(vf[0][4 * nbp], vf[0][4 * nbp + 1], vf[0][4 * nbp + 2], vf[0][4 * nbp + 3],
                   sm_b + (vbh + nbp * 16 + voff) * 2);

        // ---- Online softmax; exp via ex2.f16x2 -> P in fragment form --------
#pragma unroll
        for (int n = 0; n < 8; n++)
#pragma unroll
            for (int j = 0; j < 4; j++) s[n][j] *= SC;

        float alpha[2];
        uint32_t ph2[8][2];
#pragma unroll
        for (int hr = 0; hr < 2; hr++) {
            float mx = -INFINITY;
#pragma unroll
            for (int n = 0; n < 8; n++)
                mx = fmaxf(mx, fmaxf(s[n][2 * hr], s[n][2 * hr + 1]));
            mx = fmaxf(mx, __shfl_xor_sync(0xffffffffu, mx, 1));
            mx = fmaxf(mx, __shfl_xor_sync(0xffffffffu, mx, 2));
            float mn = fmaxf(mrun[hr], mx);
            alpha[hr] = exp2f(mrun[hr] - mn);
            float sum = 0.f;
#pragma unroll
            for (int n = 0; n < 8; n++) {
                __half2 hh = __floats2half2_rn(s[n][2 * hr] - mn, s[n][2 * hr + 1] - mn);
                uint32_t e = ex2_f16x2(h2u(hh));
                ph2[n][hr] = e;
                float2 f = __half22float2(*reinterpret_cast<__half2*>(&e));
                sum += f.x + f.y;
            }
            sum += __shfl_xor_sync(0xffffffffu, sum, 1);
            sum += __shfl_xor_sync(0xffffffffu, sum, 2);
            lsum[hr] = lsum[hr] * alpha[hr] + sum;
            mrun[hr] = mn;
        }
#pragma unroll
        for (int n = 0; n < 16; n++) {
            o[n][0] *= alpha[0]; o[n][1] *= alpha[0];
            o[n][2] *= alpha[1]; o[n][3] *= alpha[1];
        }

        // ---- O += P V, V-fragments double-buffered across k-steps -----------
#pragma unroll
        for (int kk = 0; kk < 4; kk++) {
            const int cur = kk & 1;
            if (kk < 3) {
#pragma unroll
                for (int nbp = 0; nbp < 8; nbp++)
                    ldsm4t(vf[cur ^ 1][4 * nbp], vf[cur ^ 1][4 * nbp + 1],
                           vf[cur ^ 1][4 * nbp + 2], vf[cur ^ 1][4 * nbp + 3],
                           sm_b + (vbh + (kk + 1) * 16 * KT + nbp * 16 + voff) * 2);
            }
            uint32_t a[4] = {ph2[2 * kk][0], ph2[2 * kk][1],
                             ph2[2 * kk + 1][0], ph2[2 * kk + 1][1]};
#pragma unroll
            for (int nbp = 0; nbp < 8; nbp++) {
                mma_f16(o[2 * nbp],     a, vf[cur][4 * nbp],     vf[cur][4 * nbp + 1]);
                mma_f16(o[2 * nbp + 1], a, vf[cur][4 * nbp + 2], vf[cur][4 * nbp + 3]);
            }
        }
        __syncthreads();   // stage fully consumed before its refill
    }

    const float inv0 = 1.f / lsum[0];
    const float inv1 = 1.f / lsum[1];
    const size_t orow  = (size_t)b * T_ * H_ + (size_t)(q0 + warp * 16 + g) * H_;
    const size_t orow8 = orow + (size_t)8 * H_;
#pragma unroll
    for (int n = 0; n < 16; n++) {
        int cc = n * 8 + 2 * t4;
        *reinterpret_cast<float2*>(&out[orow + cc]) =
            make_float2(o[n][0] * inv0, o[n][1] * inv0);
        *reinterpret_cast<float2*>(&out[orow8 + cc]) =
            make_float2(o[n][2] * inv1, o[n][3] * inv1);
    }
}

extern "C" void kernel_launch(void* const* d_in, const int* in_sizes, int n_in,
                              void* d_out, int out_size)
{
    (void)in_sizes; (void)n_in; (void)out_size;
    const float* x  = (const float*)d_in[0];
    const float* Wk = (const float*)d_in[1];
    const float* Wq = (const float*)d_in[2];
    const float* Wv = (const float*)d_in[3];
    float* out = (float*)d_out;

    cudaFuncSetAttribute(proj_kernel,
                         cudaFuncAttributeMaxDynamicSharedMemorySize, PROJ_SMEM);
    cudaFuncSetAttribute(attn_kernel,
                         cudaFuncAttributeMaxDynamicSharedMemorySize, ATTN_SMEM);

    cvt_x_kernel<<<B_ * T_ * C_ / (256 * 8), 256>>>(x);
    cvt_w_kernel<<<3 * H_ * C_ / 256, 256>>>(Wq, Wk, Wv);

    proj_kernel<<<16384 / 128, 256, PROJ_SMEM>>>();

    dim3 agrid(T_ / 128, B_);
    attn_kernel<<<agrid, 256, ATTN_SMEM>>>(out);
}

// round 8
// speedup vs baseline: 1.1559x; 1.0146x over previous
#include <cuda_runtime.h>
#include <cuda_fp16.h>
#include <cstdint>
#include <math.h>

#define B_ 4
#define T_ 4096
#define C_ 1024
#define H_ 128

// fp16 staging (static: allocation-free per harness rules)
__device__ __half g_X [B_ * T_ * C_];     // x as fp16            [bt][k]
__device__ __half g_WT[3 * H_ * C_];      // W^T fp16             [which][n][k]
__device__ __half g_Q [B_ * T_ * H_];
__device__ __half g_K [B_ * T_ * H_];
__device__ __half g_V [B_ * T_ * H_];

__device__ __forceinline__ uint32_t h2u(__half2 h) { return *reinterpret_cast<uint32_t*>(&h); }

__device__ __forceinline__ void mma_f16(float c[4], const uint32_t a[4],
                                        uint32_t b0, uint32_t b1) {
    asm volatile(
        "mma.sync.aligned.m16n8k16.row.col.f32.f16.f16.f32 "
        "{%0,%1,%2,%3}, {%4,%5,%6,%7}, {%8,%9}, {%0,%1,%2,%3};"
        : "+f"(c[0]), "+f"(c[1]), "+f"(c[2]), "+f"(c[3])
        : "r"(a[0]), "r"(a[1]), "r"(a[2]), "r"(a[3]), "r"(b0), "r"(b1));
}
__device__ __forceinline__ void ldsm4(uint32_t& r0, uint32_t& r1, uint32_t& r2,
                                      uint32_t& r3, uint32_t addr) {
    asm volatile("ldmatrix.sync.aligned.m8n8.x4.shared.b16 {%0,%1,%2,%3}, [%4];"
                 : "=r"(r0), "=r"(r1), "=r"(r2), "=r"(r3) : "r"(addr));
}
__device__ __forceinline__ void ldsm4t(uint32_t& r0, uint32_t& r1, uint32_t& r2,
                                       uint32_t& r3, uint32_t addr) {
    asm volatile("ldmatrix.sync.aligned.m8n8.x4.trans.shared.b16 {%0,%1,%2,%3}, [%4];"
                 : "=r"(r0), "=r"(r1), "=r"(r2), "=r"(r3) : "r"(addr));
}
__device__ __forceinline__ void cp16(uint32_t dst, const void* src) {
    asm volatile("cp.async.cg.shared.global [%0], [%1], 16;" :: "r"(dst), "l"(src));
}
__device__ __forceinline__ uint32_t ex2_f16x2(uint32_t x) {
    uint32_t r;
    asm("ex2.approx.f16x2 %0, %1;" : "=r"(r) : "r"(x));
    return r;
}

// ---------------------------------------------------------------------------
// Conversion kernels (HBM bound, one-shot)
// ---------------------------------------------------------------------------
__global__ __launch_bounds__(256)
void cvt_x_kernel(const float* __restrict__ x)
{
    int i = (blockIdx.x * 256 + threadIdx.x) * 8;
    float4 a = *reinterpret_cast<const float4*>(x + i);
    float4 b = *reinterpret_cast<const float4*>(x + i + 4);
    uint4 o;
    o.x = h2u(__floats2half2_rn(a.x, a.y));
    o.y = h2u(__floats2half2_rn(a.z, a.w));
    o.z = h2u(__floats2half2_rn(b.x, b.y));
    o.w = h2u(__floats2half2_rn(b.z, b.w));
    *reinterpret_cast<uint4*>(&g_X[i]) = o;
}

__global__ __launch_bounds__(256)
void cvt_w_kernel(const float* __restrict__ Wq,
                  const float* __restrict__ Wk,
                  const float* __restrict__ Wv)
{
    int idx = blockIdx.x * 256 + threadIdx.x;       // 3*128*1024
    int which = idx >> 17;
    int r = idx & 131071;
    int n = r >> 10, k = r & 1023;
    const float* W = (which == 0) ? Wq : (which == 1) ? Wk : Wv;
    g_WT[idx] = __float2half(W[k * H_ + n]);
}

// ---------------------------------------------------------------------------
// Fused projection: Q,K,V = X @ {Wq,Wk,Wv} in ONE kernel.
// CTA = 128 m-rows; k-chunks of 64; 3-stage cp.async pipeline, 1 sync/chunk.
// ---------------------------------------------------------------------------
#define PJ 72                           // halves per tile row (64 + 8 pad)
#define PJT (128 * PJ)                  // halves per [128 x 64] tile
#define PSTG (4 * PJT)                  // halves per stage (A + 3 W)
#define PROJ_SMEM (3 * PSTG * 2)        // 221184 B

__global__ __launch_bounds__(256)
void proj_kernel()
{
    extern __shared__ __half psm[];
    const uint32_t sm_b = (uint32_t)__cvta_generic_to_shared(psm);

    const int tid  = threadIdx.x;
    const int warp = tid >> 5;
    const int lane = tid & 31;
    const int g    = lane >> 2;
    const int t4   = lane & 3;
    const int m0   = blockIdx.x * 128;
    const __half* __restrict__ Asrc = g_X + (size_t)m0 * C_;

    const int aoff = ((lane & 8) + (lane & 7)) * PJ + ((lane & 16) >> 1);
    const int koff = (((lane & 16) >> 1) + (lane & 7)) * PJ + ((lane & 8) ? 8 : 0);

    float acc[3][16][4];
#pragma unroll
    for (int w = 0; w < 3; w++)
#pragma unroll
        for (int i = 0; i < 16; i++)
#pragma unroll
            for (int j = 0; j < 4; j++) acc[w][i][j] = 0.f;

    auto fill = [&](int c, int stg) {
        uint32_t base = sm_b + (uint32_t)stg * PSTG * 2;
        int kb = c * 64;
#pragma unroll
        for (int it = 0; it < 4; it++) {
            int u = tid + it * 256;
            int row = u >> 3, q = u & 7;
            cp16(base + (row * PJ + q * 8) * 2, Asrc + (size_t)row * C_ + kb + q * 8);
        }
#pragma unroll
        for (int w = 0; w < 3; w++) {
#pragma unroll
            for (int it = 0; it < 4; it++) {
                int u = tid + it * 256;
                int row = u >> 3, q = u & 7;
                cp16(base + ((1 + w) * PJT + row * PJ + q * 8) * 2,
                     g_WT + (size_t)w * H_ * C_ + (size_t)row * C_ + kb + q * 8);
            }
        }
        asm volatile("cp.async.commit_group;");
    };

    fill(0, 0);
    fill(1, 1);

    for (int c = 0; c < 16; c++) {
        if (c < 15) asm volatile("cp.async.wait_group 1;");
        else        asm volatile("cp.async.wait_group 0;");
        __syncthreads();
        if (c + 2 < 16) fill(c + 2, (c + 2) % 3);

        const uint32_t base = sm_b + (uint32_t)(c % 3) * PSTG * 2;
#pragma unroll
        for (int kk = 0; kk < 4; kk++) {
            uint32_t a[4];
            ldsm4(a[0], a[1], a[2], a[3],
                  base + (warp * 16 * PJ + kk * 16 + aoff) * 2);
#pragma unroll
            for (int w = 0; w < 3; w++) {
#pragma unroll
                for (int nbp = 0; nbp < 8; nbp++) {
                    uint32_t b0, b1, b2, b3;
                    ldsm4(b0, b1, b2, b3,
                          base + ((1 + w) * PJT + nbp * 16 * PJ + kk * 16 + koff) * 2);
                    mma_f16(acc[w][2 * nbp],     a, b0, b1);
                    mma_f16(acc[w][2 * nbp + 1], a, b2, b3);
                }
            }
        }
    }

    const int r0 = m0 + warp * 16 + g;
#pragma unroll
    for (int w = 0; w < 3; w++) {
        __half* outp = (w == 0) ? g_Q : (w == 1) ? g_K : g_V;
#pragma unroll
        for (int nb = 0; nb < 16; nb++) {
            int cc = nb * 8 + 2 * t4;
            *reinterpret_cast<uint32_t*>(&outp[(size_t)r0 * H_ + cc]) =
                h2u(__floats2half2_rn(acc[w][nb][0], acc[w][nb][1]));
            *reinterpret_cast<uint32_t*>(&outp[(size_t)(r0 + 8) * H_ + cc]) =
                h2u(__floats2half2_rn(acc[w][nb][2], acc[w][nb][3]));
        }
    }
}

// ---------------------------------------------------------------------------
// Flash attention: CTA = (batch, 128 q-rows), 8 warps, KV tile 128,
// 3-stage cp.async pipeline, 1 sync/tile. P stays in registers.
// ---------------------------------------------------------------------------
#define KT 136
#define VOFF (128 * KT)                 // V offset within a stage (halves)
#define ST_H (2 * 128 * KT)             // halves per stage (K + V)
#define ATTN_SMEM (3 * ST_H * 2)        // 208896 B
#define NTILES (T_ / 128)               // 32

__global__ __launch_bounds__(256)
void attn_kernel(float* __restrict__ out)
{
    extern __shared__ __half sm[];
    const uint32_t sm_b = (uint32_t)__cvta_generic_to_shared(sm);

    const int tid  = threadIdx.x;
    const int warp = tid >> 5;
    const int lane = tid & 31;
    const int g    = lane >> 2;
    const int t4   = lane & 3;
    const int b    = blockIdx.y;
    const int q0   = blockIdx.x * 128;

    const __half* __restrict__ Q = g_Q + (size_t)b * T_ * H_;
    const __half* __restrict__ K = g_K + (size_t)b * T_ * H_;
    const __half* __restrict__ V = g_V + (size_t)b * T_ * H_;

    const int koff = (((lane & 16) >> 1) + (lane & 7)) * KT + ((lane & 8) ? 8 : 0);
    const int voff = ((lane & 8) + (lane & 7)) * KT + ((lane & 16) >> 1);

    // Q fragments, direct global loads (fp16 bits)
    uint32_t qa[8][4];
    const int rg  = q0 + warp * 16 + g;
    const int rg8 = rg + 8;
#pragma unroll
    for (int kk = 0; kk < 8; kk++) {
        qa[kk][0] = *reinterpret_cast<const uint32_t*>(&Q[(size_t)rg  * H_ + kk * 16 + 2 * t4]);
        qa[kk][1] = *reinterpret_cast<const uint32_t*>(&Q[(size_t)rg8 * H_ + kk * 16 + 2 * t4]);
        qa[kk][2] = *reinterpret_cast<const uint32_t*>(&Q[(size_t)rg  * H_ + kk * 16 + 2 * t4 + 8]);
        qa[kk][3] = *reinterpret_cast<const uint32_t*>(&Q[(size_t)rg8 * H_ + kk * 16 + 2 * t4 + 8]);
    }

    float o[16][4];
#pragma unroll
    for (int i = 0; i < 16; i++)
#pragma unroll
        for (int j = 0; j < 4; j++) o[i][j] = 0.f;

    float mrun[2] = {-INFINITY, -INFINITY};
    float lsum[2] = {0.f, 0.f};
    const float SC = 0.04508422f;     // 1024^-0.5 * log2(e)

    // Fill one 128-row KV tile (K + V) into stage stg: 16 cp16 per thread.
    auto fill = [&](int t, int stg) {
        uint32_t base = sm_b + (uint32_t)stg * ST_H * 2;
#pragma unroll
        for (int it = 0; it < 16; it++) {
            int u = tid + it * 256;
            int isv = u >> 11;                 // 0: K rows, 1: V rows
            int row = (u & 2047) >> 4;
            int q   = u & 15;
            const __half* src = (isv ? V : K) + (size_t)(t * 128 + row) * H_ + q * 8;
            cp16(base + (uint32_t)(isv * VOFF + row * KT + q * 8) * 2, src);
        }
        asm volatile("cp.async.commit_group;");
    };

    fill(0, 0);
    fill(1, 1);

    for (int i = 0; i < NTILES; i++) {
        if (i < NTILES - 1) asm volatile("cp.async.wait_group 1;");
        else                asm volatile("cp.async.wait_group 0;");
        __syncthreads();
        if (i + 2 < NTILES) fill(i + 2, (i + 2) % 3);

        const uint32_t kbh = (uint32_t)(i % 3) * ST_H;
        const uint32_t vbh = kbh + VOFF;

        // ---- S = Q K^T : 16 x 128 per warp ----------------------------------
        float s[16][4];
#pragma unroll
        for (int n = 0; n < 16; n++)
#pragma unroll
            for (int j = 0; j < 4; j++) s[n][j] = 0.f;
#pragma unroll
        for (int kk = 0; kk < 8; kk++) {
#pragma unroll
            for (int nbp = 0; nbp < 8; nbp++) {
                uint32_t b0, b1, b2, b3;
                ldsm4(b0, b1, b2, b3,
                      sm_b + (kbh + nbp * 16 * KT + kk * 16 + koff) * 2);
                mma_f16(s[2 * nbp],     qa[kk], b0, b1);
                mma_f16(s[2 * nbp + 1], qa[kk], b2, b3);
            }
        }

        // ---- Online softmax; exp via ex2.f16x2 -> P in fragment form --------
#pragma unroll
        for (int n = 0; n < 16; n++)
#pragma unroll
            for (int j = 0; j < 4; j++) s[n][j] *= SC;

        float alpha[2];
        uint32_t ph2[16][2];
#pragma unroll
        for (int hr = 0; hr < 2; hr++) {
            float mx = -INFINITY;
#pragma unroll
            for (int n = 0; n < 16; n++)
                mx = fmaxf(mx, fmaxf(s[n][2 * hr], s[n][2 * hr + 1]));
            mx = fmaxf(mx, __shfl_xor_sync(0xffffffffu, mx, 1));
            mx = fmaxf(mx, __shfl_xor_sync(0xffffffffu, mx, 2));
            float mn = fmaxf(mrun[hr], mx);
            alpha[hr] = exp2f(mrun[hr] - mn);
            float sum = 0.f;
#pragma unroll
            for (int n = 0; n < 16; n++) {
                __half2 hh = __floats2half2_rn(s[n][2 * hr] - mn, s[n][2 * hr + 1] - mn);
                uint32_t e = ex2_f16x2(h2u(hh));
                ph2[n][hr] = e;
                float2 f = __half22float2(*reinterpret_cast<__half2*>(&e));
                sum += f.x + f.y;
            }
            sum += __shfl_xor_sync(0xffffffffu, sum, 1);
            sum += __shfl_xor_sync(0xffffffffu, sum, 2);
            lsum[hr] = lsum[hr] * alpha[hr] + sum;
            mrun[hr] = mn;
        }
#pragma unroll
        for (int n = 0; n < 16; n++) {
            o[n][0] *= alpha[0]; o[n][1] *= alpha[0];
            o[n][2] *= alpha[1]; o[n][3] *= alpha[1];
        }

        // ---- O += P V : k = 128 (8 steps), n = 128 (16 tiles) ----------------
#pragma unroll
        for (int kk = 0; kk < 8; kk++) {
            uint32_t a[4] = {ph2[2 * kk][0], ph2[2 * kk][1],
                             ph2[2 * kk + 1][0], ph2[2 * kk + 1][1]};
#pragma unroll
            for (int nbp = 0; nbp < 8; nbp++) {
                uint32_t b0, b1, b2, b3;
                ldsm4t(b0, b1, b2, b3,
                       sm_b + (vbh + kk * 16 * KT + nbp * 16 + voff) * 2);
                mma_f16(o[2 * nbp],     a, b0, b1);
                mma_f16(o[2 * nbp + 1], a, b2, b3);
            }
        }
    }

    const float inv0 = 1.f / lsum[0];
    const float inv1 = 1.f / lsum[1];
    const size_t orow  = (size_t)b * T_ * H_ + (size_t)(q0 + warp * 16 + g) * H_;
    const size_t orow8 = orow + (size_t)8 * H_;
#pragma unroll
    for (int n = 0; n < 16; n++) {
        int cc = n * 8 + 2 * t4;
        *reinterpret_cast<float2*>(&out[orow + cc]) =
            make_float2(o[n][0] * inv0, o[n][1] * inv0);
        *reinterpret_cast<float2*>(&out[orow8 + cc]) =
            make_float2(o[n][2] * inv1, o[n][3] * inv1);
    }
}

extern "C" void kernel_launch(void* const* d_in, const int* in_sizes, int n_in,
                              void* d_out, int out_size)
{
    (void)in_sizes; (void)n_in; (void)out_size;
    const float* x  = (const float*)d_in[0];
    const float* Wk = (const float*)d_in[1];
    const float* Wq = (const float*)d_in[2];
    const float* Wv = (const float*)d_in[3];
    float* out = (float*)d_out;

    cudaFuncSetAttribute(proj_kernel,
                         cudaFuncAttributeMaxDynamicSharedMemorySize, PROJ_SMEM);
    cudaFuncSetAttribute(attn_kernel,
                         cudaFuncAttributeMaxDynamicSharedMemorySize, ATTN_SMEM);

    cvt_x_kernel<<<B_ * T_ * C_ / (256 * 8), 256>>>(x);
    cvt_w_kernel<<<3 * H_ * C_ / 256, 256>>>(Wq, Wk, Wv);

    proj_kernel<<<16384 / 128, 256, PROJ_SMEM>>>();

    dim3 agrid(T_ / 128, B_);
    attn_kernel<<<agrid, 256, ATTN_SMEM>>>(out);
}